// round 15
// baseline (speedup 1.0000x reference)
#include <cuda_runtime.h>
#include <cstdint>

#define FULLMASK 0xffffffffu
typedef unsigned long long ull;

constexpr int Bb = 4;
constexpr int N1 = 8192, S1 = 2048, K1 = 32, C1 = 128;
constexpr int N2 = 2048, S2 = 256,  K2 = 16, C2 = 693;
constexpr int SMAX = 693;
constexpr int NCELL = 512;       // 8x8x8 spatial cells (Morton order)

// ------------- static device scratch (no runtime allocation allowed) -------------
__device__ float4 g_pack1[Bb * N1];     // (x,y,z,||p||^2) level-1 coords
__device__ float4 g_spts[Bb * N1];      // level-1 sorted (x,y,z,oidx-bits)
__device__ float4 g_spts2[Bb * N2];     // level-2 sorted
__device__ int    g_hist[Bb * NCELL];
__device__ int    g_cellofs[Bb * NCELL];    // after scatter: END offsets (level 1)
__device__ int    g_hist2[Bb * NCELL];
__device__ int    g_cellofs2[Bb * NCELL];
__device__ float4 g_cent1[Bb * S1];     // l1 centers (= l1_xyz), with norms
__device__ float4 g_cent2[Bb * S2];     // l2 centers
__device__ int    g_fps1[Bb * S1];
__device__ int    g_fps2[Bb * S2];
__device__ int    g_ball1[Bb * S1 * K1];
__device__ int    g_ball2[Bb * S2 * K2];
__device__ float  g_h2[(size_t)Bb * S2 * K2 * C2];   // ~45 MB
__device__ float  g_l1pts[(size_t)Bb * S1 * C1];
__device__ double g_sums[2 * SMAX];
__device__ float  g_mu[SMAX];
__device__ float  g_rs[SMAX];

// ---------------- packed f32x2 helpers (each lane = IEEE rn op, identical to scalar) ----------------
__device__ __forceinline__ ull pk2(float a, float b) {
    ull r; asm("mov.b64 %0,{%1,%2};" : "=l"(r) : "f"(a), "f"(b)); return r;
}
__device__ __forceinline__ void upk2(ull v, float& a, float& b) {
    asm("mov.b64 {%0,%1},%2;" : "=f"(a), "=f"(b) : "l"(v));
}
__device__ __forceinline__ ull f2add(ull a, ull b) {
    ull r; asm("add.rn.f32x2 %0,%1,%2;" : "=l"(r) : "l"(a), "l"(b)); return r;
}
__device__ __forceinline__ ull f2mul(ull a, ull b) {
    ull r; asm("mul.rn.f32x2 %0,%1,%2;" : "=l"(r) : "l"(a), "l"(b)); return r;
}

// (x^2 + y^2) + z^2 with explicit rounding (no FMA contraction) — matches
// XLA's elementwise mul + sequential axis(-1) reduce.
__device__ __forceinline__ float sq3(float x, float y, float z) {
    return __fadd_rn(__fadd_rn(__fmul_rn(x, x), __fmul_rn(y, y)), __fmul_rn(z, z));
}

// ---------------- Morton cell index ----------------
__device__ __forceinline__ int morton3(int cx, int cy, int cz) {
    int m = 0;
#pragma unroll
    for (int i = 0; i < 3; i++) {
        m |= ((cz >> i) & 1) << (3 * i + 0);
        m |= ((cy >> i) & 1) << (3 * i + 1);
        m |= ((cx >> i) & 1) << (3 * i + 2);
    }
    return m;
}
__device__ __forceinline__ int cell_of(float x, float y, float z) {
    int cx = min(7, max(0, (int)(x * 8.0f)));
    int cy = min(7, max(0, (int)(y * 8.0f)));
    int cz = min(7, max(0, (int)(z * 8.0f)));
    return morton3(cx, cy, cz);
}

// ---------------- pack coords + squared norm ----------------
__global__ void k_pack1(const float* __restrict__ xyz, float4* __restrict__ pack) {
    int i = blockIdx.x * blockDim.x + threadIdx.x;
    if (i >= Bb * N1) return;
    float x = xyz[(size_t)i * 6 + 0];
    float y = xyz[(size_t)i * 6 + 1];
    float z = xyz[(size_t)i * 6 + 2];
    pack[i] = make_float4(x, y, z, sq3(x, y, z));
}

// ---------------- generic counting sort into Morton cells ----------------
__global__ void k_zeroi(int* __restrict__ p, int n) {
    int i = blockIdx.x * blockDim.x + threadIdx.x;
    if (i < n) p[i] = 0;
}
__global__ void k_hist(const float4* __restrict__ in, int* __restrict__ hist, int Npts) {
    int i = blockIdx.x * blockDim.x + threadIdx.x;
    if (i >= Bb * Npts) return;
    float4 v = in[i];
    atomicAdd(&hist[(i / Npts) * NCELL + cell_of(v.x, v.y, v.z)], 1);
}
__global__ void k_scan(const int* __restrict__ hist, int* __restrict__ ofs) {
    __shared__ int s[NCELL];
    int b = blockIdx.x, t = threadIdx.x;
    int h = hist[b * NCELL + t];
    s[t] = h;
    __syncthreads();
    for (int off = 1; off < NCELL; off <<= 1) {
        int v = (t >= off) ? s[t - off] : 0;
        __syncthreads();
        s[t] += v;
        __syncthreads();
    }
    ofs[b * NCELL + t] = s[t] - h;   // exclusive prefix
}
__global__ void k_scatter(const float4* __restrict__ in, int* __restrict__ ofs,
                          float4* __restrict__ outp, int Npts) {
    int i = blockIdx.x * blockDim.x + threadIdx.x;
    if (i >= Bb * Npts) return;
    int b = i / Npts;
    float4 v = in[i];
    int pos = atomicAdd(&ofs[b * NCELL + cell_of(v.x, v.y, v.z)], 1);
    outp[b * Npts + pos] = make_float4(v.x, v.y, v.z, __int_as_float(i - b * Npts));
}

// ---------------- FPS with per-thread register pruning (R13 scheme, templated) ----------------
// Thread t owns sorted positions [t*PPTF, (t+1)*PPTF) (Morton-compact). Coords
// packed f32x2, dd[], bbox, vmax in registers. Skip iff dmin2*0.998 > vmax:
// every fmin would be a no-op -> skip is BIT-EXACT. Dirty warps rerun the
// reference's exact no-FMA chain and refresh lane-uniform (wval,wkey); clean
// warps keep theirs. One barrier + redux fold per iter. key=(oidx<<13|pos)
// min -> ties resolve to lowest ORIGINAL index (jnp.argmax semantics).
template <int N, int S, int T, int PPTF>
__global__ void __launch_bounds__(T) k_fpsp(const float4* __restrict__ spts,
                                            int* __restrict__ outIdx) {
    constexpr int NW = T / 32;
    extern __shared__ float sm[];
    float* sx = sm;
    float* sy = sm + N;
    float* sz = sm + 2 * N;
    int*   soidx = (int*)(sm + 3 * N);
    __shared__ unsigned sv[2][NW];
    __shared__ int sk[2][NW];
    __shared__ int s_f0;

    int b = blockIdx.x, t = threadIdx.x;
    int w = t >> 5, l = t & 31;
    const float4* p = spts + (size_t)b * N;

    for (int i = t; i < N; i += T) {
        float4 v = p[i];
        sx[i] = v.x; sy[i] = v.y; sz[i] = v.z;
        int oi = __float_as_int(v.w);
        soidx[i] = oi;
        if (oi == 0) s_f0 = i;
    }
    __syncthreads();

    const int base = t * PPTF;
    ull px2[PPTF / 2], py2[PPTF / 2], pz2[PPTF / 2];
    float dd[PPTF];
    float bx0 = 1e30f, bx1 = -1e30f, by0 = 1e30f, by1 = -1e30f, bz0 = 1e30f, bz1 = -1e30f;
#pragma unroll
    for (int q = 0; q < PPTF / 2; q++) {
        float x0 = sx[base + 2 * q], x1 = sx[base + 2 * q + 1];
        float y0 = sy[base + 2 * q], y1 = sy[base + 2 * q + 1];
        float z0 = sz[base + 2 * q], z1 = sz[base + 2 * q + 1];
        px2[q] = pk2(x0, x1); py2[q] = pk2(y0, y1); pz2[q] = pk2(z0, z1);
        bx0 = fminf(bx0, fminf(x0, x1)); bx1 = fmaxf(bx1, fmaxf(x0, x1));
        by0 = fminf(by0, fminf(y0, y1)); by1 = fmaxf(by1, fmaxf(y0, y1));
        bz0 = fminf(bz0, fminf(z0, z1)); bz1 = fmaxf(bz1, fmaxf(z0, z1));
        dd[2 * q] = 1e10f; dd[2 * q + 1] = 1e10f;
    }
    float vmax = 1e10f;
    unsigned wval = 0u;          // lane-uniform warp candidate (set on iter 0: all dirty)
    int wkey = 0x7fffffff;

    int* oi = outIdx + b * S;
    int f = s_f0;    // sorted position of original index 0
    int wo = 0;      // original index to emit
    for (int it = 0; it < S; ++it) {
        if (t == 0) oi[it] = wo;
        float cx = sx[f], cy = sy[f], cz = sz[f];

        // value-safe pruning test (registers only)
        float dxm = fmaxf(fmaxf(bx0 - cx, cx - bx1), 0.0f);
        float dym = fmaxf(fmaxf(by0 - cy, cy - by1), 0.0f);
        float dzm = fmaxf(fmaxf(bz0 - cz, cz - bz1), 0.0f);
        float dmin2 = dxm * dxm + dym * dym + dzm * dzm;
        bool dirty = !(dmin2 * 0.998f > vmax);

        if (__any_sync(FULLMASK, dirty)) {
            ull ncx = pk2(-cx, -cx), ncy = pk2(-cy, -cy), ncz = pk2(-cz, -cz);
            float nm = __int_as_float(0xff800000);
#pragma unroll
            for (int q = 0; q < PPTF / 2; q++) {
                ull dx = f2add(px2[q], ncx);
                ull dy = f2add(py2[q], ncy);
                ull dz = f2add(pz2[q], ncz);
                ull s = f2add(f2add(f2mul(dx, dx), f2mul(dy, dy)), f2mul(dz, dz));
                float d0, d1; upk2(s, d0, d1);
                float n0 = fminf(dd[2 * q], d0);
                float n1 = fminf(dd[2 * q + 1], d1);
                dd[2 * q] = n0; dd[2 * q + 1] = n1;
                nm = fmaxf(nm, fmaxf(n0, n1));
            }
            vmax = nm;
            unsigned vb = __float_as_uint(vmax);       // dd >= 0 -> order-preserving
            unsigned wm = __reduce_max_sync(FULLMASK, vb);
            int cand = 0x7fffffff;
            if (vb == wm) {
#pragma unroll
                for (int j = 0; j < PPTF; j++)
                    if (__float_as_uint(dd[j]) == wm)
                        cand = min(cand, (soidx[base + j] << 13) | (base + j));
            }
            cand = __reduce_min_sync(FULLMASK, cand);
            wval = wm; wkey = cand;                    // lane-uniform
        }

        int par = it & 1;
        if (l == 0) { sv[par][w] = wval; sk[par][w] = wkey; }
        __syncthreads();
        unsigned u2 = (l < NW) ? sv[par][l] : 0u;
        int i2 = (l < NW) ? sk[par][l] : 0x7fffffff;
        unsigned gm = __reduce_max_sync(FULLMASK, u2);
        int kk = __reduce_min_sync(FULLMASK, (u2 == gm) ? i2 : 0x7fffffff);
        f = kk & 0x1fff;
        wo = kk >> 13;
    }
}

// ---------------- gather sampled centers (and optionally emit l2_xyz) ----------------
__global__ void k_gather(const float4* __restrict__ pack, const int* __restrict__ fps,
                         float4* __restrict__ cent, int S, int N,
                         float* __restrict__ xyzOut) {
    int i = blockIdx.x * blockDim.x + threadIdx.x;
    if (i >= Bb * S) return;
    int b = i / S;
    float4 v = pack[b * N + fps[i]];
    cent[i] = v;
    if (xyzOut) {
        xyzOut[(size_t)i * 3 + 0] = v.x;
        xyzOut[(size_t)i * 3 + 1] = v.y;
        xyzOut[(size_t)i * 3 + 2] = v.z;
    }
}

// ---------------- ball query 1: cell-culled, one warp per center ----------------
// r=0.0025 << cell 0.125. Scan the <=8 cells covering c +- (r+0.002): any
// point outside has a coordinate gap > 0.0045 -> true d^2 >= 2e-5, and the
// cancellation formula's abs error <= ~3e-6, so the reference test also
// rejects it -> identical hit SET. Same exact formula on survivors. Hits are
// sorted ascending by original index and padded with the first (= jnp.sort +
// take K + pad). q norms recomputed via sq3 (bit-identical to pack).
__global__ void k_ballc(const float4* __restrict__ spts, const int* __restrict__ cellEnd,
                        const float4* __restrict__ cent, int* __restrict__ out) {
    constexpr float R2 = (float)(0.0025 * 0.0025);
    constexpr float M = 0.0025f + 0.002f;
    __shared__ int lst[8][64];
    int lane = threadIdx.x & 31, w = threadIdx.x >> 5;
    int cid = (blockIdx.x * blockDim.x + threadIdx.x) >> 5;
    if (cid >= Bb * S1) return;
    int b = cid / S1;
    float4 c = cent[cid];
    int x0 = min(7, max(0, (int)floorf((c.x - M) * 8.0f)));
    int x1 = min(7, max(0, (int)floorf((c.x + M) * 8.0f)));
    int y0 = min(7, max(0, (int)floorf((c.y - M) * 8.0f)));
    int y1 = min(7, max(0, (int)floorf((c.y + M) * 8.0f)));
    int z0 = min(7, max(0, (int)floorf((c.z - M) * 8.0f)));
    int z1 = min(7, max(0, (int)floorf((c.z + M) * 8.0f)));
    const float4* p = spts + (size_t)b * N1;
    const int* ce = cellEnd + b * NCELL;
    int cnt = 0;
    for (int cx = x0; cx <= x1; cx++)
        for (int cy = y0; cy <= y1; cy++)
            for (int cz = z0; cz <= z1; cz++) {
                int cell = morton3(cx, cy, cz);
                int s0 = cell ? ce[cell - 1] : 0;      // Morton cells contiguous
                int e0 = ce[cell];
                for (int base = s0; base < e0; base += 32) {
                    int i = base + lane;
                    bool valid = i < e0;
                    float4 q = valid ? p[i] : make_float4(1e9f, 1e9f, 1e9f, 0.0f);
                    float qw = sq3(q.x, q.y, q.z);
                    float dot = fmaf(c.z, q.z, fmaf(c.y, q.y, __fmul_rn(c.x, q.x)));
                    float sq = __fsub_rn(__fadd_rn(c.w, qw), __fmul_rn(2.0f, dot));
                    bool in = valid && !(sq > R2);
                    unsigned bm = __ballot_sync(FULLMASK, in);
                    if (in) {
                        int pos = cnt + __popc(bm & ((1u << lane) - 1u));
                        if (pos < 64) lst[w][pos] = __float_as_int(q.w);
                    }
                    cnt += __popc(bm);
                }
            }
    cnt = min(cnt, 64);
    __syncwarp();
    if (lane == 0) {                     // insertion sort (typ. 1 hit)
        for (int i = 1; i < cnt; i++) {
            int key = lst[w][i], j = i - 1;
            while (j >= 0 && lst[w][j] > key) { lst[w][j + 1] = lst[w][j]; j--; }
            lst[w][j + 1] = key;
        }
    }
    __syncwarp();
    int first = cnt ? lst[w][0] : (N1 - 1);    // empty ball: idx n, clamped at gather
    int* o = out + (size_t)cid * K1;
    for (int k = lane; k < K1; k += 32) o[k] = (k < cnt) ? lst[w][k] : first;
}

// ---------------- ball query 2: full scan (small), one warp per center ----------------
template <int NPTS, int K>
__global__ void k_ball(const float4* __restrict__ pack, const float4* __restrict__ cent,
                       int S, float r2, int* __restrict__ out) {
    int lane = threadIdx.x & 31;
    int cid = (blockIdx.x * blockDim.x + threadIdx.x) >> 5;
    if (cid >= Bb * S) return;
    int b = cid / S;
    float4 c = cent[cid];
    const float4* p = pack + (size_t)b * NPTS;
    int* o = out + (size_t)cid * K;
    int cnt = 0, first = -1;
    for (int base = 0; base < NPTS && cnt < K; base += 128) {
        float4 q[4];
#pragma unroll
        for (int u = 0; u < 4; u++) q[u] = p[base + u * 32 + lane];
#pragma unroll
        for (int u = 0; u < 4; u++) {
            float dot = fmaf(c.z, q[u].z, fmaf(c.y, q[u].y, __fmul_rn(c.x, q[u].x)));
            float sq = __fsub_rn(__fadd_rn(c.w, q[u].w), __fmul_rn(2.0f, dot));
            bool in = !(sq > r2);
            unsigned bm = __ballot_sync(FULLMASK, in);
            if (bm) {
                int pos = cnt + __popc(bm & ((1u << lane) - 1u));
                if (in && pos < K) o[pos] = base + u * 32 + lane;
                if (first < 0) first = base + u * 32 + __ffs(bm) - 1;
                cnt += __popc(bm);
            }
        }
    }
    if (first < 0) first = NPTS - 1;
    for (int pos = min(cnt, K) + lane; pos < K; pos += 32) o[pos] = first;
}

// ---------------- zero the BN accumulators ----------------
__global__ void k_zero() {
    int i = blockIdx.x * blockDim.x + threadIdx.x;
    if (i < 2 * SMAX) g_sums[i] = 0.0;
}

// ---------------- level-1 feature gather (shared by both passes) ----------------
__device__ __forceinline__ void l1_gather(float* F, const float* __restrict__ xyz,
                                          int bs, int b, int t) {
    if (t < K1) {
        int idx = g_ball1[bs * K1 + t];
        float4 p = g_pack1[b * N1 + idx];
        float4 c = g_cent1[bs];
        const float* nr = xyz + (size_t)(b * N1 + idx) * 6 + 3;
        F[t * 6 + 0] = __fsub_rn(p.x, c.x);
        F[t * 6 + 1] = __fsub_rn(p.y, c.y);
        F[t * 6 + 2] = __fsub_rn(p.z, c.z);
        F[t * 6 + 3] = nr[0];
        F[t * 6 + 4] = nr[1];
        F[t * 6 + 5] = nr[2];
    }
}

__device__ __forceinline__ float l1_h(const float* fv, const float* w, float bias) {
    float h = fmaf(fv[0], w[0], 0.0f);
#pragma unroll
    for (int j = 1; j < 6; j++) h = fmaf(fv[j], w[j], h);
    return __fadd_rn(h, bias);
}

// ---------------- level-1 MLP pass A: statistics only ----------------
__global__ void k_mlp1(const float* __restrict__ xyz,
                       const float* __restrict__ w1, const float* __restrict__ b1) {
    __shared__ float F[K1 * 6];
    int bs = blockIdx.x, t = threadIdx.x;
    l1_gather(F, xyz, bs, bs / S1, t);
    __syncthreads();
    float w[6];
#pragma unroll
    for (int j = 0; j < 6; j++) w[j] = w1[j * C1 + t];
    float bias = b1[t];
    double ds = 0.0, dq = 0.0;
#pragma unroll 4
    for (int k = 0; k < K1; k++) {
        float h = l1_h(F + k * 6, w, bias);
        ds += (double)h;
        dq += (double)h * (double)h;
    }
    atomicAdd(&g_sums[t], ds);
    atomicAdd(&g_sums[SMAX + t], dq);
}

// ---------------- BN statistics: mu, rsqrt(var + eps) ----------------
__global__ void k_stats(int C, double M) {
    int t = blockIdx.x * blockDim.x + threadIdx.x;
    if (t >= C) return;
    double m = g_sums[t] / M;
    double var = g_sums[SMAX + t] / M - m * m;
    float vf = (float)var;
    g_mu[t] = (float)m;
    g_rs[t] = (float)(1.0 / sqrt((double)__fadd_rn(vf, 1e-5f)));
}

// ---------------- level-1 pass B: recompute h (bit-identical), normalize+relu+max ----------------
__global__ void k_nm1(const float* __restrict__ xyz,
                      const float* __restrict__ w1, const float* __restrict__ b1,
                      const float* __restrict__ g1, const float* __restrict__ be1) {
    __shared__ float F[K1 * 6];
    int bs = blockIdx.x, t = threadIdx.x;
    l1_gather(F, xyz, bs, bs / S1, t);
    __syncthreads();
    float w[6];
#pragma unroll
    for (int j = 0; j < 6; j++) w[j] = w1[j * C1 + t];
    float bias = b1[t];
    float mu = g_mu[t], rs = g_rs[t], ga = g1[t], be = be1[t];
    float m = __int_as_float(0xff800000);
#pragma unroll 4
    for (int k = 0; k < K1; k++) {
        float h = l1_h(F + k * 6, w, bias);
        float v = __fadd_rn(__fmul_rn(__fmul_rn(__fsub_rn(h, mu), rs), ga), be);
        m = fmaxf(m, fmaxf(v, 0.0f));
    }
    g_l1pts[(size_t)bs * C1 + t] = m;
}

// ---------------- level-2 MLP ----------------
__global__ void k_mlp2(const float* __restrict__ w2, const float* __restrict__ b2) {
    __shared__ __align__(16) float FT[131 * 16];   // FT[j][k], k-contiguous
    int bs = blockIdx.x, t = threadIdx.x;
    int b = bs / S2;
    for (int e = t; e < 131 * 16; e += blockDim.x) {
        int k = e / 131, j = e - k * 131;
        int idx = g_ball2[bs * K2 + k];
        float v;
        if (j < 3) {
            float4 p = g_cent1[b * N2 + idx];
            float4 c = g_cent2[bs];
            v = (j == 0) ? __fsub_rn(p.x, c.x)
              : (j == 1) ? __fsub_rn(p.y, c.y)
                         : __fsub_rn(p.z, c.z);
        } else {
            v = g_l1pts[(size_t)(b * N2 + idx) * C1 + (j - 3)];
        }
        FT[j * 16 + k] = v;
    }
    __syncthreads();
    if (t >= C2) return;
    float acc[16];
#pragma unroll
    for (int k = 0; k < 16; k++) acc[k] = 0.0f;
    for (int j = 0; j < 131; j++) {
        float wj = w2[j * C2 + t];
        const float4* fp = (const float4*)(FT + j * 16);
#pragma unroll
        for (int q = 0; q < 4; q++) {
            float4 fv = fp[q];
            acc[q * 4 + 0] = fmaf(fv.x, wj, acc[q * 4 + 0]);
            acc[q * 4 + 1] = fmaf(fv.y, wj, acc[q * 4 + 1]);
            acc[q * 4 + 2] = fmaf(fv.z, wj, acc[q * 4 + 2]);
            acc[q * 4 + 3] = fmaf(fv.w, wj, acc[q * 4 + 3]);
        }
    }
    float bias = b2[t];
    double ds = 0.0, dq = 0.0;
    float* op = g_h2 + (size_t)bs * K2 * C2 + t;
#pragma unroll
    for (int k = 0; k < 16; k++) {
        float h = __fadd_rn(acc[k], bias);
        op[(size_t)k * C2] = h;
        ds += (double)h;
        dq += (double)h * (double)h;
    }
    atomicAdd(&g_sums[t], ds);
    atomicAdd(&g_sums[SMAX + t], dq);
}

// ---------------- level-2 normalize + relu + max over k -> l2_pts ----------------
__global__ void k_nm2(const float* __restrict__ g2, const float* __restrict__ be2,
                      float* __restrict__ out) {
    int bs = blockIdx.x, c = threadIdx.x;
    if (c >= C2) return;
    float mu = g_mu[c], rs = g_rs[c], ga = g2[c], be = be2[c];
    const float* hp = g_h2 + (size_t)bs * K2 * C2 + c;
    float m = __int_as_float(0xff800000);
#pragma unroll
    for (int k = 0; k < K2; k++) {
        float h = hp[(size_t)k * C2];
        float v = __fadd_rn(__fmul_rn(__fmul_rn(__fsub_rn(h, mu), rs), ga), be);
        m = fmaxf(m, fmaxf(v, 0.0f));
    }
    out[(size_t)bs * C2 + c] = m;
}

// ==================================================================================
extern "C" void kernel_launch(void* const* d_in, const int* in_sizes, int n_in,
                              void* d_out, int out_size) {
    const float* xyz = (const float*)d_in[0];
    const float* w1  = (const float*)d_in[1];
    const float* b1  = (const float*)d_in[2];
    const float* g1  = (const float*)d_in[3];
    const float* be1 = (const float*)d_in[4];
    const float* w2  = (const float*)d_in[5];
    const float* b2  = (const float*)d_in[6];
    const float* g2  = (const float*)d_in[7];
    const float* be2 = (const float*)d_in[8];
    float* out = (float*)d_out;
    float* l2xyz = out;                    // (4,256,3)
    float* l2pts = out + Bb * S2 * 3;      // (4,256,693)

    void *pP1, *pSP, *pSP2, *pC1, *pC2, *pF1, *pF2, *pB1, *pB2;
    void *pH1, *pO1, *pH2, *pO2;
    cudaGetSymbolAddress(&pP1, g_pack1);
    cudaGetSymbolAddress(&pSP, g_spts);
    cudaGetSymbolAddress(&pSP2, g_spts2);
    cudaGetSymbolAddress(&pC1, g_cent1);
    cudaGetSymbolAddress(&pC2, g_cent2);
    cudaGetSymbolAddress(&pF1, g_fps1);
    cudaGetSymbolAddress(&pF2, g_fps2);
    cudaGetSymbolAddress(&pB1, g_ball1);
    cudaGetSymbolAddress(&pB2, g_ball2);
    cudaGetSymbolAddress(&pH1, g_hist);
    cudaGetSymbolAddress(&pO1, g_cellofs);
    cudaGetSymbolAddress(&pH2, g_hist2);
    cudaGetSymbolAddress(&pO2, g_cellofs2);
    float4* P1 = (float4*)pP1;
    float4* SP1 = (float4*)pSP;
    float4* SP2 = (float4*)pSP2;
    float4* Cn1 = (float4*)pC1;
    float4* Cn2 = (float4*)pC2;
    int* F1 = (int*)pF1;
    int* F2 = (int*)pF2;
    int* Ball1 = (int*)pB1;
    int* Ball2 = (int*)pB2;
    int* H1 = (int*)pH1;
    int* O1 = (int*)pO1;
    int* H2 = (int*)pH2;
    int* O2 = (int*)pO2;

    const float r2_2 = (float)(0.005 * 0.005);

    const int smemA = 4 * N1 * (int)sizeof(float);            // 128 KB
    const int smemB = 4 * N2 * (int)sizeof(float);            // 32 KB
    cudaFuncSetAttribute((const void*)k_fpsp<N1, S1, 512, 16>,
                         cudaFuncAttributeMaxDynamicSharedMemorySize, smemA);
    cudaFuncSetAttribute((const void*)k_fpsp<N2, S2, 512, 4>,
                         cudaFuncAttributeMaxDynamicSharedMemorySize, smemB);

    // ---- level 1 ----
    k_pack1<<<(Bb * N1 + 255) / 256, 256>>>(xyz, P1);
    k_zeroi<<<(Bb * NCELL + 255) / 256, 256>>>(H1, Bb * NCELL);
    k_hist<<<(Bb * N1 + 255) / 256, 256>>>(P1, H1, N1);
    k_scan<<<Bb, NCELL>>>(H1, O1);
    k_scatter<<<(Bb * N1 + 255) / 256, 256>>>(P1, O1, SP1, N1);   // O1 -> end offsets
    k_fpsp<N1, S1, 512, 16><<<Bb, 512, smemA>>>(SP1, F1);
    k_gather<<<(Bb * S1 + 255) / 256, 256>>>(P1, F1, Cn1, S1, N1, nullptr);
    k_ballc<<<(Bb * S1) / 8, 256>>>(SP1, O1, Cn1, Ball1);
    k_zero<<<2, 704>>>();
    k_mlp1<<<Bb * S1, C1>>>(xyz, w1, b1);
    k_stats<<<1, 704>>>(C1, (double)(Bb * S1 * K1));
    k_nm1<<<Bb * S1, C1>>>(xyz, w1, b1, g1, be1);

    // ---- level 2 ----
    k_zeroi<<<(Bb * NCELL + 255) / 256, 256>>>(H2, Bb * NCELL);
    k_hist<<<(Bb * N2 + 255) / 256, 256>>>(Cn1, H2, N2);
    k_scan<<<Bb, NCELL>>>(H2, O2);
    k_scatter<<<(Bb * N2 + 255) / 256, 256>>>(Cn1, O2, SP2, N2);
    k_fpsp<N2, S2, 512, 4><<<Bb, 512, smemB>>>(SP2, F2);
    k_gather<<<(Bb * S2 + 255) / 256, 256>>>(Cn1, F2, Cn2, S2, N2, l2xyz);
    k_ball<N2, K2><<<(Bb * S2) / 8, 256>>>(Cn1, Cn2, S2, r2_2, Ball2);
    k_zero<<<2, 704>>>();
    k_mlp2<<<Bb * S2, 704>>>(w2, b2);
    k_stats<<<1, 704>>>(C2, (double)(Bb * S2 * K2));
    k_nm2<<<Bb * S2, 704>>>(g2, be2, l2pts);
}

// round 16
// speedup vs baseline: 1.2151x; 1.2151x over previous
#include <cuda_runtime.h>
#include <cstdint>

#define FULLMASK 0xffffffffu
typedef unsigned long long ull;

constexpr int Bb = 4;
constexpr int N1 = 8192, S1 = 2048, K1 = 32, C1 = 128;
constexpr int N2 = 2048, S2 = 256,  K2 = 16, C2 = 693;
constexpr int SMAX = 693;
constexpr int NCELL = 512;       // 8x8x8 spatial cells (Morton order)

// ------------- static device scratch (no runtime allocation allowed) -------------
__device__ float4 g_pack1[Bb * N1];     // (x,y,z,||p||^2) level-1 coords
__device__ float4 g_spts[Bb * N1];      // level-1 sorted (x,y,z,oidx-bits)
__device__ float4 g_spts2[Bb * N2];     // level-2 sorted
__device__ int    g_hist[Bb * NCELL];
__device__ int    g_cellofs[Bb * NCELL];    // after scatter: END offsets (level 1)
__device__ int    g_hist2[Bb * NCELL];
__device__ int    g_cellofs2[Bb * NCELL];
__device__ float4 g_cent1[Bb * S1];     // l1 centers (= l1_xyz), with norms
__device__ float4 g_cent2[Bb * S2];     // l2 centers
__device__ int    g_fps1[Bb * S1];
__device__ int    g_fps2[Bb * S2];
__device__ int    g_ball1[Bb * S1 * K1];
__device__ int    g_ball2[Bb * S2 * K2];
__device__ float  g_h2[(size_t)Bb * S2 * K2 * C2];   // ~45 MB
__device__ float  g_l1pts[(size_t)Bb * S1 * C1];
__device__ double g_sums[2 * SMAX];
__device__ float  g_mu[SMAX];
__device__ float  g_rs[SMAX];

// ---------------- packed f32x2 helpers (each lane = IEEE rn op, identical to scalar) ----------------
__device__ __forceinline__ ull pk2(float a, float b) {
    ull r; asm("mov.b64 %0,{%1,%2};" : "=l"(r) : "f"(a), "f"(b)); return r;
}
__device__ __forceinline__ void upk2(ull v, float& a, float& b) {
    asm("mov.b64 {%0,%1},%2;" : "=f"(a), "=f"(b) : "l"(v));
}
__device__ __forceinline__ ull f2add(ull a, ull b) {
    ull r; asm("add.rn.f32x2 %0,%1,%2;" : "=l"(r) : "l"(a), "l"(b)); return r;
}
__device__ __forceinline__ ull f2mul(ull a, ull b) {
    ull r; asm("mul.rn.f32x2 %0,%1,%2;" : "=l"(r) : "l"(a), "l"(b)); return r;
}

// (x^2 + y^2) + z^2 with explicit rounding (no FMA contraction) — matches
// XLA's elementwise mul + sequential axis(-1) reduce.
__device__ __forceinline__ float sq3(float x, float y, float z) {
    return __fadd_rn(__fadd_rn(__fmul_rn(x, x), __fmul_rn(y, y)), __fmul_rn(z, z));
}

// ---------------- Morton cell index ----------------
__device__ __forceinline__ int morton3(int cx, int cy, int cz) {
    int m = 0;
#pragma unroll
    for (int i = 0; i < 3; i++) {
        m |= ((cz >> i) & 1) << (3 * i + 0);
        m |= ((cy >> i) & 1) << (3 * i + 1);
        m |= ((cx >> i) & 1) << (3 * i + 2);
    }
    return m;
}
__device__ __forceinline__ int cell_of(float x, float y, float z) {
    int cx = min(7, max(0, (int)(x * 8.0f)));
    int cy = min(7, max(0, (int)(y * 8.0f)));
    int cz = min(7, max(0, (int)(z * 8.0f)));
    return morton3(cx, cy, cz);
}

// ---------------- pack coords + squared norm ----------------
__global__ void k_pack1(const float* __restrict__ xyz, float4* __restrict__ pack) {
    int i = blockIdx.x * blockDim.x + threadIdx.x;
    if (i >= Bb * N1) return;
    float x = xyz[(size_t)i * 6 + 0];
    float y = xyz[(size_t)i * 6 + 1];
    float z = xyz[(size_t)i * 6 + 2];
    pack[i] = make_float4(x, y, z, sq3(x, y, z));
}

// ---------------- generic counting sort into Morton cells ----------------
__global__ void k_zeroi(int* __restrict__ p, int n) {
    int i = blockIdx.x * blockDim.x + threadIdx.x;
    if (i < n) p[i] = 0;
}
__global__ void k_hist(const float4* __restrict__ in, int* __restrict__ hist, int Npts) {
    int i = blockIdx.x * blockDim.x + threadIdx.x;
    if (i >= Bb * Npts) return;
    float4 v = in[i];
    atomicAdd(&hist[(i / Npts) * NCELL + cell_of(v.x, v.y, v.z)], 1);
}
__global__ void k_scan(const int* __restrict__ hist, int* __restrict__ ofs) {
    __shared__ int s[NCELL];
    int b = blockIdx.x, t = threadIdx.x;
    int h = hist[b * NCELL + t];
    s[t] = h;
    __syncthreads();
    for (int off = 1; off < NCELL; off <<= 1) {
        int v = (t >= off) ? s[t - off] : 0;
        __syncthreads();
        s[t] += v;
        __syncthreads();
    }
    ofs[b * NCELL + t] = s[t] - h;   // exclusive prefix
}
__global__ void k_scatter(const float4* __restrict__ in, int* __restrict__ ofs,
                          float4* __restrict__ outp, int Npts) {
    int i = blockIdx.x * blockDim.x + threadIdx.x;
    if (i >= Bb * Npts) return;
    int b = i / Npts;
    float4 v = in[i];
    int pos = atomicAdd(&ofs[b * NCELL + cell_of(v.x, v.y, v.z)], 1);
    outp[b * Npts + pos] = make_float4(v.x, v.y, v.z, __int_as_float(i - b * Npts));
}

// ---------------- FPS with per-thread register pruning (R13 scheme, templated) ----------------
// Thread t owns sorted positions [t*PPTF, (t+1)*PPTF) (Morton-compact). Coords
// packed f32x2, dd[], bbox, vmax in registers. Skip iff dmin2*0.998 > vmax:
// every fmin would be a no-op -> skip is BIT-EXACT. Dirty warps rerun the
// reference's exact no-FMA chain and refresh lane-uniform (wval,wkey); clean
// warps keep theirs. One barrier + redux fold per iter. key=(oidx<<13|pos)
// min -> ties resolve to lowest ORIGINAL index (jnp.argmax semantics).
template <int N, int S, int T, int PPTF>
__global__ void __launch_bounds__(T) k_fpsp(const float4* __restrict__ spts,
                                            int* __restrict__ outIdx) {
    constexpr int NW = T / 32;
    extern __shared__ float sm[];
    float* sx = sm;
    float* sy = sm + N;
    float* sz = sm + 2 * N;
    int*   soidx = (int*)(sm + 3 * N);
    __shared__ unsigned sv[2][NW];
    __shared__ int sk[2][NW];
    __shared__ int s_f0;

    int b = blockIdx.x, t = threadIdx.x;
    int w = t >> 5, l = t & 31;
    const float4* p = spts + (size_t)b * N;

    for (int i = t; i < N; i += T) {
        float4 v = p[i];
        sx[i] = v.x; sy[i] = v.y; sz[i] = v.z;
        int oi = __float_as_int(v.w);
        soidx[i] = oi;
        if (oi == 0) s_f0 = i;
    }
    __syncthreads();

    const int base = t * PPTF;
    ull px2[PPTF / 2], py2[PPTF / 2], pz2[PPTF / 2];
    float dd[PPTF];
    float bx0 = 1e30f, bx1 = -1e30f, by0 = 1e30f, by1 = -1e30f, bz0 = 1e30f, bz1 = -1e30f;
#pragma unroll
    for (int q = 0; q < PPTF / 2; q++) {
        float x0 = sx[base + 2 * q], x1 = sx[base + 2 * q + 1];
        float y0 = sy[base + 2 * q], y1 = sy[base + 2 * q + 1];
        float z0 = sz[base + 2 * q], z1 = sz[base + 2 * q + 1];
        px2[q] = pk2(x0, x1); py2[q] = pk2(y0, y1); pz2[q] = pk2(z0, z1);
        bx0 = fminf(bx0, fminf(x0, x1)); bx1 = fmaxf(bx1, fmaxf(x0, x1));
        by0 = fminf(by0, fminf(y0, y1)); by1 = fmaxf(by1, fmaxf(y0, y1));
        bz0 = fminf(bz0, fminf(z0, z1)); bz1 = fmaxf(bz1, fmaxf(z0, z1));
        dd[2 * q] = 1e10f; dd[2 * q + 1] = 1e10f;
    }
    float vmax = 1e10f;
    unsigned wval = 0u;          // lane-uniform warp candidate (set on iter 0: all dirty)
    int wkey = 0x7fffffff;

    int* oi = outIdx + b * S;
    int f = s_f0;    // sorted position of original index 0
    int wo = 0;      // original index to emit
    for (int it = 0; it < S; ++it) {
        if (t == 0) oi[it] = wo;
        float cx = sx[f], cy = sy[f], cz = sz[f];

        // value-safe pruning test (registers only)
        float dxm = fmaxf(fmaxf(bx0 - cx, cx - bx1), 0.0f);
        float dym = fmaxf(fmaxf(by0 - cy, cy - by1), 0.0f);
        float dzm = fmaxf(fmaxf(bz0 - cz, cz - bz1), 0.0f);
        float dmin2 = dxm * dxm + dym * dym + dzm * dzm;
        bool dirty = !(dmin2 * 0.998f > vmax);

        if (__any_sync(FULLMASK, dirty)) {
            ull ncx = pk2(-cx, -cx), ncy = pk2(-cy, -cy), ncz = pk2(-cz, -cz);
            float nm = __int_as_float(0xff800000);
#pragma unroll
            for (int q = 0; q < PPTF / 2; q++) {
                ull dx = f2add(px2[q], ncx);
                ull dy = f2add(py2[q], ncy);
                ull dz = f2add(pz2[q], ncz);
                ull s = f2add(f2add(f2mul(dx, dx), f2mul(dy, dy)), f2mul(dz, dz));
                float d0, d1; upk2(s, d0, d1);
                float n0 = fminf(dd[2 * q], d0);
                float n1 = fminf(dd[2 * q + 1], d1);
                dd[2 * q] = n0; dd[2 * q + 1] = n1;
                nm = fmaxf(nm, fmaxf(n0, n1));
            }
            vmax = nm;
            unsigned vb = __float_as_uint(vmax);       // dd >= 0 -> order-preserving
            unsigned wm = __reduce_max_sync(FULLMASK, vb);
            int cand = 0x7fffffff;
            if (vb == wm) {
#pragma unroll
                for (int j = 0; j < PPTF; j++)
                    if (__float_as_uint(dd[j]) == wm)
                        cand = min(cand, (soidx[base + j] << 13) | (base + j));
            }
            cand = __reduce_min_sync(FULLMASK, cand);
            wval = wm; wkey = cand;                    // lane-uniform
        }

        int par = it & 1;
        if (l == 0) { sv[par][w] = wval; sk[par][w] = wkey; }
        __syncthreads();
        unsigned u2 = (l < NW) ? sv[par][l] : 0u;
        int i2 = (l < NW) ? sk[par][l] : 0x7fffffff;
        unsigned gm = __reduce_max_sync(FULLMASK, u2);
        int kk = __reduce_min_sync(FULLMASK, (u2 == gm) ? i2 : 0x7fffffff);
        f = kk & 0x1fff;
        wo = kk >> 13;
    }
}

// ---------------- gather sampled centers (and optionally emit l2_xyz) ----------------
__global__ void k_gather(const float4* __restrict__ pack, const int* __restrict__ fps,
                         float4* __restrict__ cent, int S, int N,
                         float* __restrict__ xyzOut) {
    int i = blockIdx.x * blockDim.x + threadIdx.x;
    if (i >= Bb * S) return;
    int b = i / S;
    float4 v = pack[b * N + fps[i]];
    cent[i] = v;
    if (xyzOut) {
        xyzOut[(size_t)i * 3 + 0] = v.x;
        xyzOut[(size_t)i * 3 + 1] = v.y;
        xyzOut[(size_t)i * 3 + 2] = v.z;
    }
}

// ---------------- ball query 1: cell-culled, one warp per center ----------------
// r=0.0025 << cell 0.125. Scan the <=8 cells covering c +- (r+0.002): any
// point outside has a coordinate gap > 0.0045 -> true d^2 >= 2e-5, and the
// cancellation formula's abs error <= ~3e-6, so the reference test also
// rejects it -> identical hit SET. Same exact formula on survivors. Hits are
// sorted ascending by original index and padded with the first (= jnp.sort +
// take K + pad). q norms recomputed via sq3 (bit-identical to pack).
__global__ void k_ballc(const float4* __restrict__ spts, const int* __restrict__ cellEnd,
                        const float4* __restrict__ cent, int* __restrict__ out) {
    constexpr float R2 = (float)(0.0025 * 0.0025);
    constexpr float M = 0.0025f + 0.002f;
    __shared__ int lst[8][64];
    int lane = threadIdx.x & 31, w = threadIdx.x >> 5;
    int cid = (blockIdx.x * blockDim.x + threadIdx.x) >> 5;
    if (cid >= Bb * S1) return;
    int b = cid / S1;
    float4 c = cent[cid];
    int x0 = min(7, max(0, (int)floorf((c.x - M) * 8.0f)));
    int x1 = min(7, max(0, (int)floorf((c.x + M) * 8.0f)));
    int y0 = min(7, max(0, (int)floorf((c.y - M) * 8.0f)));
    int y1 = min(7, max(0, (int)floorf((c.y + M) * 8.0f)));
    int z0 = min(7, max(0, (int)floorf((c.z - M) * 8.0f)));
    int z1 = min(7, max(0, (int)floorf((c.z + M) * 8.0f)));
    const float4* p = spts + (size_t)b * N1;
    const int* ce = cellEnd + b * NCELL;
    int cnt = 0;
    for (int cx = x0; cx <= x1; cx++)
        for (int cy = y0; cy <= y1; cy++)
            for (int cz = z0; cz <= z1; cz++) {
                int cell = morton3(cx, cy, cz);
                int s0 = cell ? ce[cell - 1] : 0;      // Morton cells contiguous
                int e0 = ce[cell];
                for (int base = s0; base < e0; base += 32) {
                    int i = base + lane;
                    bool valid = i < e0;
                    float4 q = valid ? p[i] : make_float4(1e9f, 1e9f, 1e9f, 0.0f);
                    float qw = sq3(q.x, q.y, q.z);
                    float dot = fmaf(c.z, q.z, fmaf(c.y, q.y, __fmul_rn(c.x, q.x)));
                    float sq = __fsub_rn(__fadd_rn(c.w, qw), __fmul_rn(2.0f, dot));
                    bool in = valid && !(sq > R2);
                    unsigned bm = __ballot_sync(FULLMASK, in);
                    if (in) {
                        int pos = cnt + __popc(bm & ((1u << lane) - 1u));
                        if (pos < 64) lst[w][pos] = __float_as_int(q.w);
                    }
                    cnt += __popc(bm);
                }
            }
    cnt = min(cnt, 64);
    __syncwarp();
    if (lane == 0) {                     // insertion sort (typ. 1 hit)
        for (int i = 1; i < cnt; i++) {
            int key = lst[w][i], j = i - 1;
            while (j >= 0 && lst[w][j] > key) { lst[w][j + 1] = lst[w][j]; j--; }
            lst[w][j + 1] = key;
        }
    }
    __syncwarp();
    int first = cnt ? lst[w][0] : (N1 - 1);    // empty ball: idx n, clamped at gather
    int* o = out + (size_t)cid * K1;
    for (int k = lane; k < K1; k += 32) o[k] = (k < cnt) ? lst[w][k] : first;
}

// ---------------- ball query 2: full scan (small), one warp per center ----------------
template <int NPTS, int K>
__global__ void k_ball(const float4* __restrict__ pack, const float4* __restrict__ cent,
                       int S, float r2, int* __restrict__ out) {
    int lane = threadIdx.x & 31;
    int cid = (blockIdx.x * blockDim.x + threadIdx.x) >> 5;
    if (cid >= Bb * S) return;
    int b = cid / S;
    float4 c = cent[cid];
    const float4* p = pack + (size_t)b * NPTS;
    int* o = out + (size_t)cid * K;
    int cnt = 0, first = -1;
    for (int base = 0; base < NPTS && cnt < K; base += 128) {
        float4 q[4];
#pragma unroll
        for (int u = 0; u < 4; u++) q[u] = p[base + u * 32 + lane];
#pragma unroll
        for (int u = 0; u < 4; u++) {
            float dot = fmaf(c.z, q[u].z, fmaf(c.y, q[u].y, __fmul_rn(c.x, q[u].x)));
            float sq = __fsub_rn(__fadd_rn(c.w, q[u].w), __fmul_rn(2.0f, dot));
            bool in = !(sq > r2);
            unsigned bm = __ballot_sync(FULLMASK, in);
            if (bm) {
                int pos = cnt + __popc(bm & ((1u << lane) - 1u));
                if (in && pos < K) o[pos] = base + u * 32 + lane;
                if (first < 0) first = base + u * 32 + __ffs(bm) - 1;
                cnt += __popc(bm);
            }
        }
    }
    if (first < 0) first = NPTS - 1;
    for (int pos = min(cnt, K) + lane; pos < K; pos += 32) o[pos] = first;
}

// ---------------- zero the BN accumulators ----------------
__global__ void k_zero() {
    int i = blockIdx.x * blockDim.x + threadIdx.x;
    if (i < 2 * SMAX) g_sums[i] = 0.0;
}

// ---------------- level-1 feature gather (shared by both passes) ----------------
__device__ __forceinline__ void l1_gather(float* F, const float* __restrict__ xyz,
                                          int bs, int b, int t) {
    if (t < K1) {
        int idx = g_ball1[bs * K1 + t];
        float4 p = g_pack1[b * N1 + idx];
        float4 c = g_cent1[bs];
        const float* nr = xyz + (size_t)(b * N1 + idx) * 6 + 3;
        F[t * 6 + 0] = __fsub_rn(p.x, c.x);
        F[t * 6 + 1] = __fsub_rn(p.y, c.y);
        F[t * 6 + 2] = __fsub_rn(p.z, c.z);
        F[t * 6 + 3] = nr[0];
        F[t * 6 + 4] = nr[1];
        F[t * 6 + 5] = nr[2];
    }
}

__device__ __forceinline__ float l1_h(const float* fv, const float* w, float bias) {
    float h = fmaf(fv[0], w[0], 0.0f);
#pragma unroll
    for (int j = 1; j < 6; j++) h = fmaf(fv[j], w[j], h);
    return __fadd_rn(h, bias);
}

// ---------------- level-1 MLP pass A: statistics only ----------------
__global__ void k_mlp1(const float* __restrict__ xyz,
                       const float* __restrict__ w1, const float* __restrict__ b1) {
    __shared__ float F[K1 * 6];
    int bs = blockIdx.x, t = threadIdx.x;
    l1_gather(F, xyz, bs, bs / S1, t);
    __syncthreads();
    float w[6];
#pragma unroll
    for (int j = 0; j < 6; j++) w[j] = w1[j * C1 + t];
    float bias = b1[t];
    double ds = 0.0, dq = 0.0;
#pragma unroll 4
    for (int k = 0; k < K1; k++) {
        float h = l1_h(F + k * 6, w, bias);
        ds += (double)h;
        dq += (double)h * (double)h;
    }
    atomicAdd(&g_sums[t], ds);
    atomicAdd(&g_sums[SMAX + t], dq);
}

// ---------------- BN statistics: mu, rsqrt(var + eps) ----------------
__global__ void k_stats(int C, double M) {
    int t = blockIdx.x * blockDim.x + threadIdx.x;
    if (t >= C) return;
    double m = g_sums[t] / M;
    double var = g_sums[SMAX + t] / M - m * m;
    float vf = (float)var;
    g_mu[t] = (float)m;
    g_rs[t] = (float)(1.0 / sqrt((double)__fadd_rn(vf, 1e-5f)));
}

// ---------------- level-1 pass B: recompute h (bit-identical), normalize+relu+max ----------------
__global__ void k_nm1(const float* __restrict__ xyz,
                      const float* __restrict__ w1, const float* __restrict__ b1,
                      const float* __restrict__ g1, const float* __restrict__ be1) {
    __shared__ float F[K1 * 6];
    int bs = blockIdx.x, t = threadIdx.x;
    l1_gather(F, xyz, bs, bs / S1, t);
    __syncthreads();
    float w[6];
#pragma unroll
    for (int j = 0; j < 6; j++) w[j] = w1[j * C1 + t];
    float bias = b1[t];
    float mu = g_mu[t], rs = g_rs[t], ga = g1[t], be = be1[t];
    float m = __int_as_float(0xff800000);
#pragma unroll 4
    for (int k = 0; k < K1; k++) {
        float h = l1_h(F + k * 6, w, bias);
        float v = __fadd_rn(__fmul_rn(__fmul_rn(__fsub_rn(h, mu), rs), ga), be);
        m = fmaxf(m, fmaxf(v, 0.0f));
    }
    g_l1pts[(size_t)bs * C1 + t] = m;
}

// ---------------- level-2 MLP ----------------
__global__ void k_mlp2(const float* __restrict__ w2, const float* __restrict__ b2) {
    __shared__ __align__(16) float FT[131 * 16];   // FT[j][k], k-contiguous
    int bs = blockIdx.x, t = threadIdx.x;
    int b = bs / S2;
    for (int e = t; e < 131 * 16; e += blockDim.x) {
        int k = e / 131, j = e - k * 131;
        int idx = g_ball2[bs * K2 + k];
        float v;
        if (j < 3) {
            float4 p = g_cent1[b * N2 + idx];
            float4 c = g_cent2[bs];
            v = (j == 0) ? __fsub_rn(p.x, c.x)
              : (j == 1) ? __fsub_rn(p.y, c.y)
                         : __fsub_rn(p.z, c.z);
        } else {
            v = g_l1pts[(size_t)(b * N2 + idx) * C1 + (j - 3)];
        }
        FT[j * 16 + k] = v;
    }
    __syncthreads();
    if (t >= C2) return;
    float acc[16];
#pragma unroll
    for (int k = 0; k < 16; k++) acc[k] = 0.0f;
    for (int j = 0; j < 131; j++) {
        float wj = w2[j * C2 + t];
        const float4* fp = (const float4*)(FT + j * 16);
#pragma unroll
        for (int q = 0; q < 4; q++) {
            float4 fv = fp[q];
            acc[q * 4 + 0] = fmaf(fv.x, wj, acc[q * 4 + 0]);
            acc[q * 4 + 1] = fmaf(fv.y, wj, acc[q * 4 + 1]);
            acc[q * 4 + 2] = fmaf(fv.z, wj, acc[q * 4 + 2]);
            acc[q * 4 + 3] = fmaf(fv.w, wj, acc[q * 4 + 3]);
        }
    }
    float bias = b2[t];
    double ds = 0.0, dq = 0.0;
    float* op = g_h2 + (size_t)bs * K2 * C2 + t;
#pragma unroll
    for (int k = 0; k < 16; k++) {
        float h = __fadd_rn(acc[k], bias);
        op[(size_t)k * C2] = h;
        ds += (double)h;
        dq += (double)h * (double)h;
    }
    atomicAdd(&g_sums[t], ds);
    atomicAdd(&g_sums[SMAX + t], dq);
}

// ---------------- level-2 normalize + relu + max over k -> l2_pts ----------------
__global__ void k_nm2(const float* __restrict__ g2, const float* __restrict__ be2,
                      float* __restrict__ out) {
    int bs = blockIdx.x, c = threadIdx.x;
    if (c >= C2) return;
    float mu = g_mu[c], rs = g_rs[c], ga = g2[c], be = be2[c];
    const float* hp = g_h2 + (size_t)bs * K2 * C2 + c;
    float m = __int_as_float(0xff800000);
#pragma unroll
    for (int k = 0; k < K2; k++) {
        float h = hp[(size_t)k * C2];
        float v = __fadd_rn(__fmul_rn(__fmul_rn(__fsub_rn(h, mu), rs), ga), be);
        m = fmaxf(m, fmaxf(v, 0.0f));
    }
    out[(size_t)bs * C2 + c] = m;
}

// ==================================================================================
extern "C" void kernel_launch(void* const* d_in, const int* in_sizes, int n_in,
                              void* d_out, int out_size) {
    const float* xyz = (const float*)d_in[0];
    const float* w1  = (const float*)d_in[1];
    const float* b1  = (const float*)d_in[2];
    const float* g1  = (const float*)d_in[3];
    const float* be1 = (const float*)d_in[4];
    const float* w2  = (const float*)d_in[5];
    const float* b2  = (const float*)d_in[6];
    const float* g2  = (const float*)d_in[7];
    const float* be2 = (const float*)d_in[8];
    float* out = (float*)d_out;
    float* l2xyz = out;                    // (4,256,3)
    float* l2pts = out + Bb * S2 * 3;      // (4,256,693)

    void *pP1, *pSP, *pSP2, *pC1, *pC2, *pF1, *pF2, *pB1, *pB2;
    void *pH1, *pO1, *pH2, *pO2;
    cudaGetSymbolAddress(&pP1, g_pack1);
    cudaGetSymbolAddress(&pSP, g_spts);
    cudaGetSymbolAddress(&pSP2, g_spts2);
    cudaGetSymbolAddress(&pC1, g_cent1);
    cudaGetSymbolAddress(&pC2, g_cent2);
    cudaGetSymbolAddress(&pF1, g_fps1);
    cudaGetSymbolAddress(&pF2, g_fps2);
    cudaGetSymbolAddress(&pB1, g_ball1);
    cudaGetSymbolAddress(&pB2, g_ball2);
    cudaGetSymbolAddress(&pH1, g_hist);
    cudaGetSymbolAddress(&pO1, g_cellofs);
    cudaGetSymbolAddress(&pH2, g_hist2);
    cudaGetSymbolAddress(&pO2, g_cellofs2);
    float4* P1 = (float4*)pP1;
    float4* SP1 = (float4*)pSP;
    float4* SP2 = (float4*)pSP2;
    float4* Cn1 = (float4*)pC1;
    float4* Cn2 = (float4*)pC2;
    int* F1 = (int*)pF1;
    int* F2 = (int*)pF2;
    int* Ball1 = (int*)pB1;
    int* Ball2 = (int*)pB2;
    int* H1 = (int*)pH1;
    int* O1 = (int*)pO1;
    int* H2 = (int*)pH2;
    int* O2 = (int*)pO2;

    const float r2_2 = (float)(0.005 * 0.005);

    const int smemA = 4 * N1 * (int)sizeof(float);            // 128 KB
    const int smemB = 4 * N2 * (int)sizeof(float);            // 32 KB
    cudaFuncSetAttribute((const void*)k_fpsp<N1, S1, 1024, 8>,
                         cudaFuncAttributeMaxDynamicSharedMemorySize, smemA);
    cudaFuncSetAttribute((const void*)k_fpsp<N2, S2, 512, 4>,
                         cudaFuncAttributeMaxDynamicSharedMemorySize, smemB);

    // ---- level 1 ----
    k_pack1<<<(Bb * N1 + 255) / 256, 256>>>(xyz, P1);
    k_zeroi<<<(Bb * NCELL + 255) / 256, 256>>>(H1, Bb * NCELL);
    k_hist<<<(Bb * N1 + 255) / 256, 256>>>(P1, H1, N1);
    k_scan<<<Bb, NCELL>>>(H1, O1);
    k_scatter<<<(Bb * N1 + 255) / 256, 256>>>(P1, O1, SP1, N1);   // O1 -> end offsets
    k_fpsp<N1, S1, 1024, 8><<<Bb, 1024, smemA>>>(SP1, F1);
    k_gather<<<(Bb * S1 + 255) / 256, 256>>>(P1, F1, Cn1, S1, N1, nullptr);
    k_ballc<<<(Bb * S1) / 8, 256>>>(SP1, O1, Cn1, Ball1);
    k_zero<<<2, 704>>>();
    k_mlp1<<<Bb * S1, C1>>>(xyz, w1, b1);
    k_stats<<<1, 704>>>(C1, (double)(Bb * S1 * K1));
    k_nm1<<<Bb * S1, C1>>>(xyz, w1, b1, g1, be1);

    // ---- level 2 ----
    k_zeroi<<<(Bb * NCELL + 255) / 256, 256>>>(H2, Bb * NCELL);
    k_hist<<<(Bb * N2 + 255) / 256, 256>>>(Cn1, H2, N2);
    k_scan<<<Bb, NCELL>>>(H2, O2);
    k_scatter<<<(Bb * N2 + 255) / 256, 256>>>(Cn1, O2, SP2, N2);
    k_fpsp<N2, S2, 512, 4><<<Bb, 512, smemB>>>(SP2, F2);
    k_gather<<<(Bb * S2 + 255) / 256, 256>>>(Cn1, F2, Cn2, S2, N2, l2xyz);
    k_ball<N2, K2><<<(Bb * S2) / 8, 256>>>(Cn1, Cn2, S2, r2_2, Ball2);
    k_zero<<<2, 704>>>();
    k_mlp2<<<Bb * S2, 704>>>(w2, b2);
    k_stats<<<1, 704>>>(C2, (double)(Bb * S2 * K2));
    k_nm2<<<Bb * S2, 704>>>(g2, be2, l2pts);
}